// round 2
// baseline (speedup 1.0000x reference)
#include <cuda_runtime.h>
#include <math.h>

#define NMAX 50000
#define EMAX 800000

// ---------------- scratch (device globals: no runtime allocation allowed) ----------------
__device__ __align__(16) float g_h1[(size_t)NMAX * 256];
__device__ __align__(16) float g_agg1[(size_t)NMAX * 256];
__device__ __align__(16) float g_z1[(size_t)NMAX * 256];
__device__ __align__(16) float g_h2[(size_t)NMAX * 256];
__device__ __align__(16) float g_agg2[(size_t)NMAX * 256];
__device__ __align__(16) float g_z2[(size_t)NMAX * 256];
__device__ __align__(16) float g_as1[NMAX * 2];
__device__ __align__(16) float g_ad1[NMAX * 2];
__device__ __align__(16) float g_s1[NMAX * 2];
__device__ __align__(16) float g_as2[NMAX];
__device__ __align__(16) float g_ad2[NMAX];
__device__ __align__(16) float g_s2[NMAX];

// ---------------- zero accumulators ----------------
__global__ void zero_kernel(int N) {
    size_t total = (size_t)N * 256;
    size_t stride = (size_t)gridDim.x * blockDim.x;
    for (size_t i = (size_t)blockIdx.x * blockDim.x + threadIdx.x; i < total; i += stride) {
        g_agg1[i] = 0.f;
        g_agg2[i] = 0.f;
        if (i < (size_t)N * 2) g_s1[i] = 0.f;
        if (i < (size_t)N)     g_s2[i] = 0.f;
    }
}

// ---------------- SGEMM: C[n][o] = sum_k A[n][k] * B[o][k]; K=O=256 ----------------
// asel: 0 -> Aext, 1 -> g_z1 ; csel: 0 -> g_h1, 1 -> g_h2
__global__ __launch_bounds__(256) void sgemm_nt64(
    const float* __restrict__ Aext, const float* __restrict__ B,
    int asel, int csel, int N)
{
    const int BM = 64, BK = 32, K = 256, O = 256;
    const float* A = (asel == 0) ? Aext : g_z1;
    float* C = (csel == 0) ? g_h1 : g_h2;

    __shared__ float As[BK][BM + 4];
    __shared__ float Bs[BK][BM + 4];
    int bm = blockIdx.x * BM;
    int bn = blockIdx.y * 64;
    int tid = threadIdx.x;
    int tr = tid >> 4, tc = tid & 15;

    float acc[4][4];
#pragma unroll
    for (int i = 0; i < 4; i++)
#pragma unroll
        for (int j = 0; j < 4; j++) acc[i][j] = 0.f;

    for (int kt = 0; kt < K; kt += BK) {
#pragma unroll
        for (int i = 0; i < 2; i++) {
            int e = tid + i * 256;
            int row = e >> 3, kq = e & 7;
            int gn = bm + row;
            float4 v = make_float4(0.f, 0.f, 0.f, 0.f);
            if (gn < N) v = *(const float4*)(A + (size_t)gn * K + kt + kq * 4);
            As[kq * 4 + 0][row] = v.x; As[kq * 4 + 1][row] = v.y;
            As[kq * 4 + 2][row] = v.z; As[kq * 4 + 3][row] = v.w;
        }
#pragma unroll
        for (int i = 0; i < 2; i++) {
            int e = tid + i * 256;
            int row = e >> 3, kq = e & 7;
            float4 v = *(const float4*)(B + (size_t)(bn + row) * K + kt + kq * 4);
            Bs[kq * 4 + 0][row] = v.x; Bs[kq * 4 + 1][row] = v.y;
            Bs[kq * 4 + 2][row] = v.z; Bs[kq * 4 + 3][row] = v.w;
        }
        __syncthreads();
#pragma unroll
        for (int kk = 0; kk < BK; kk++) {
            float4 a = *(const float4*)&As[kk][tr * 4];
            float4 b = *(const float4*)&Bs[kk][tc * 4];
            float av[4] = {a.x, a.y, a.z, a.w};
            float bv[4] = {b.x, b.y, b.z, b.w};
#pragma unroll
            for (int i = 0; i < 4; i++)
#pragma unroll
                for (int j = 0; j < 4; j++) acc[i][j] += av[i] * bv[j];
        }
        __syncthreads();
    }
#pragma unroll
    for (int i = 0; i < 4; i++) {
        int gn = bm + tr * 4 + i;
        if (gn < N) {
            float4 v = make_float4(acc[i][0], acc[i][1], acc[i][2], acc[i][3]);
            *(float4*)(C + (size_t)gn * O + bn + tc * 4) = v;
        }
    }
}

// ---------------- attention scalars ----------------
__global__ void alpha_l1(const float* __restrict__ asv, const float* __restrict__ adv, int N) {
    int w = (int)(((size_t)blockIdx.x * blockDim.x + threadIdx.x) >> 5);
    int lane = threadIdx.x & 31;
    if (w >= N) return;
    const float* row = g_h1 + (size_t)w * 256;
    float s0 = 0.f, s1 = 0.f, d0 = 0.f, d1 = 0.f;
#pragma unroll
    for (int t = lane; t < 128; t += 32) {
        float v0 = row[t], v1 = row[128 + t];
        s0 += v0 * asv[t];       d0 += v0 * adv[t];
        s1 += v1 * asv[128 + t]; d1 += v1 * adv[128 + t];
    }
#pragma unroll
    for (int o = 16; o; o >>= 1) {
        s0 += __shfl_xor_sync(0xffffffffu, s0, o);
        s1 += __shfl_xor_sync(0xffffffffu, s1, o);
        d0 += __shfl_xor_sync(0xffffffffu, d0, o);
        d1 += __shfl_xor_sync(0xffffffffu, d1, o);
    }
    if (lane == 0) {
        g_as1[w * 2] = s0; g_as1[w * 2 + 1] = s1;
        g_ad1[w * 2] = d0; g_ad1[w * 2 + 1] = d1;
    }
}

__global__ void alpha_l2(const float* __restrict__ asv, const float* __restrict__ adv, int N) {
    int w = (int)(((size_t)blockIdx.x * blockDim.x + threadIdx.x) >> 5);
    int lane = threadIdx.x & 31;
    if (w >= N) return;
    const float* row = g_h2 + (size_t)w * 256;
    float s = 0.f, d = 0.f;
#pragma unroll
    for (int t = lane; t < 256; t += 32) {
        float v = row[t];
        s += v * asv[t]; d += v * adv[t];
    }
#pragma unroll
    for (int o = 16; o; o >>= 1) {
        s += __shfl_xor_sync(0xffffffffu, s, o);
        d += __shfl_xor_sync(0xffffffffu, d, o);
    }
    if (lane == 0) { g_as2[w] = s; g_ad2[w] = d; }
}

// ---------------- edge passes: one warp per edge (incl. self-loops) ----------------
// Unnormalized accumulation: agg[dst] += exp(lrelu(as[src]+ad[dst])) * h[src]; s[dst] += exp(...)
__global__ __launch_bounds__(256) void edge_l1(const int* __restrict__ src,
                                               const int* __restrict__ dst,
                                               int E, int N)
{
    int w = (int)(((size_t)blockIdx.x * blockDim.x + threadIdx.x) >> 5);
    int lane = threadIdx.x & 31;
    if (w >= E + N) return;
    int s, d;
    if (w < E) { s = src[w]; d = dst[w]; } else { s = d = w - E; }
    float e0 = g_as1[s * 2]     + g_ad1[d * 2];
    float e1 = g_as1[s * 2 + 1] + g_ad1[d * 2 + 1];
    e0 = e0 > 0.f ? e0 : 0.2f * e0;
    e1 = e1 > 0.f ? e1 : 0.2f * e1;
    float p0 = __expf(e0), p1 = __expf(e1);
    if (lane == 0) {
        atomicAdd(&g_s1[d * 2], p0);
        atomicAdd(&g_s1[d * 2 + 1], p1);
    }
    const float4* hs = (const float4*)(g_h1 + (size_t)s * 256);
    float* ag = g_agg1 + (size_t)d * 256;
    float4 v0 = hs[lane];       // head 0 : floats [lane*4 .. lane*4+3]  (<128)
    float4 v1 = hs[32 + lane];  // head 1
    int o0 = lane * 4, o1 = 128 + lane * 4;
    atomicAdd(&ag[o0 + 0], p0 * v0.x);
    atomicAdd(&ag[o0 + 1], p0 * v0.y);
    atomicAdd(&ag[o0 + 2], p0 * v0.z);
    atomicAdd(&ag[o0 + 3], p0 * v0.w);
    atomicAdd(&ag[o1 + 0], p1 * v1.x);
    atomicAdd(&ag[o1 + 1], p1 * v1.y);
    atomicAdd(&ag[o1 + 2], p1 * v1.z);
    atomicAdd(&ag[o1 + 3], p1 * v1.w);
}

__global__ __launch_bounds__(256) void edge_l2(const int* __restrict__ src,
                                               const int* __restrict__ dst,
                                               int E, int N)
{
    int w = (int)(((size_t)blockIdx.x * blockDim.x + threadIdx.x) >> 5);
    int lane = threadIdx.x & 31;
    if (w >= E + N) return;
    int s, d;
    if (w < E) { s = src[w]; d = dst[w]; } else { s = d = w - E; }
    float e = g_as2[s] + g_ad2[d];
    e = e > 0.f ? e : 0.2f * e;
    float p = __expf(e);
    if (lane == 0) atomicAdd(&g_s2[d], p);
    const float4* hs = (const float4*)(g_h2 + (size_t)s * 256);
    float* ag = g_agg2 + (size_t)d * 256;
    float4 v0 = hs[lane];
    float4 v1 = hs[32 + lane];
    int o0 = lane * 4, o1 = 128 + lane * 4;
    atomicAdd(&ag[o0 + 0], p * v0.x);
    atomicAdd(&ag[o0 + 1], p * v0.y);
    atomicAdd(&ag[o0 + 2], p * v0.z);
    atomicAdd(&ag[o0 + 3], p * v0.w);
    atomicAdd(&ag[o1 + 0], p * v1.x);
    atomicAdd(&ag[o1 + 1], p * v1.y);
    atomicAdd(&ag[o1 + 2], p * v1.z);
    atomicAdd(&ag[o1 + 3], p * v1.w);
}

// ---------------- node epilogues ----------------
__global__ void epi_l1(const float* __restrict__ b, int N) {
    size_t i = (size_t)blockIdx.x * blockDim.x + threadIdx.x;
    if (i >= (size_t)N * 256) return;
    int n = (int)(i >> 8);
    int t = (int)(i & 255);
    float v = g_agg1[i] / g_s1[n * 2 + (t >> 7)] + b[t];
    g_z1[i] = v > 0.f ? v : 0.01f * v;   // F.leaky_relu default slope
}

__global__ void epi_l2(const float* __restrict__ b, int N) {
    size_t i = (size_t)blockIdx.x * blockDim.x + threadIdx.x;
    if (i >= (size_t)N * 256) return;
    int n = (int)(i >> 8);
    int t = (int)(i & 255);
    g_z2[i] = g_agg2[i] / g_s2[n] + b[t];  // heads=1, mean = identity; no activation
}

// ---------------- fused projection + cosine similarity ----------------
// out[n][kb] = cos( z2[n,:] @ G[:, kb*128 .. kb*128+127], mu[kb,:] )
__global__ __launch_bounds__(256) void gemm_g_cos(
    const float* __restrict__ G, const float* __restrict__ mu,
    float* __restrict__ out, int N)
{
    const int BM = 64, BK = 32, K = 256, OC = 1024;
    __shared__ float As[BK][BM + 4];
    __shared__ float Bs[BK][128 + 4];
    int bm = blockIdx.x * BM;
    int kb = blockIdx.y;        // 0..7
    int bn = kb * 128;
    int tid = threadIdx.x;
    int tr = tid >> 4, tc = tid & 15;

    float acc[4][8];
#pragma unroll
    for (int i = 0; i < 4; i++)
#pragma unroll
        for (int j = 0; j < 8; j++) acc[i][j] = 0.f;

    for (int kt = 0; kt < K; kt += BK) {
#pragma unroll
        for (int i = 0; i < 2; i++) {
            int e = tid + i * 256;
            int row = e >> 3, kq = e & 7;
            int gn = bm + row;
            float4 v = make_float4(0.f, 0.f, 0.f, 0.f);
            if (gn < N) v = *(const float4*)(g_z2 + (size_t)gn * K + kt + kq * 4);
            As[kq * 4 + 0][row] = v.x; As[kq * 4 + 1][row] = v.y;
            As[kq * 4 + 2][row] = v.z; As[kq * 4 + 3][row] = v.w;
        }
#pragma unroll
        for (int i = 0; i < 4; i++) {
            int e = tid + i * 256;
            int row = e >> 5, cq = e & 31;
            float4 v = *(const float4*)(G + (size_t)(kt + row) * OC + bn + cq * 4);
            *(float4*)&Bs[row][cq * 4] = v;
        }
        __syncthreads();
#pragma unroll
        for (int kk = 0; kk < BK; kk++) {
            float4 a  = *(const float4*)&As[kk][tr * 4];
            float4 b0 = *(const float4*)&Bs[kk][tc * 8];
            float4 b1 = *(const float4*)&Bs[kk][tc * 8 + 4];
            float av[4] = {a.x, a.y, a.z, a.w};
            float bv[8] = {b0.x, b0.y, b0.z, b0.w, b1.x, b1.y, b1.z, b1.w};
#pragma unroll
            for (int i = 0; i < 4; i++)
#pragma unroll
                for (int j = 0; j < 8; j++) acc[i][j] += av[i] * bv[j];
        }
        __syncthreads();
    }

    // cosine epilogue: each 16-thread group (same tr) owns 4 rows x 128 cols
    const float* muk = mu + kb * 128;
    float mj[8], musq = 0.f;
#pragma unroll
    for (int j = 0; j < 8; j++) { mj[j] = muk[tc * 8 + j]; musq += mj[j] * mj[j]; }
    float num[4], sq[4];
#pragma unroll
    for (int i = 0; i < 4; i++) {
        float n_ = 0.f, s_ = 0.f;
#pragma unroll
        for (int j = 0; j < 8; j++) { n_ += acc[i][j] * mj[j]; s_ += acc[i][j] * acc[i][j]; }
        num[i] = n_; sq[i] = s_;
    }
#pragma unroll
    for (int o = 8; o; o >>= 1) {
        musq += __shfl_xor_sync(0xffffffffu, musq, o);
#pragma unroll
        for (int i = 0; i < 4; i++) {
            num[i] += __shfl_xor_sync(0xffffffffu, num[i], o);
            sq[i]  += __shfl_xor_sync(0xffffffffu, sq[i], o);
        }
    }
    if (tc == 0) {
        float mun = sqrtf(musq);
#pragma unroll
        for (int i = 0; i < 4; i++) {
            int gn = bm + tr * 4 + i;
            if (gn < N) {
                float denom = fmaxf(sqrtf(sq[i]) * mun, 1e-8f);
                out[(size_t)gn * 8 + kb] = num[i] / denom;
            }
        }
    }
}

// ---------------- launch ----------------
extern "C" void kernel_launch(void* const* d_in, const int* in_sizes, int n_in,
                              void* d_out, int out_size)
{
    const float* x      = (const float*)d_in[0];
    const int*   ei     = (const int*)d_in[1];      // JAX default x64-disabled: int32!
    const float* W1     = (const float*)d_in[2];
    const float* a_src1 = (const float*)d_in[3];
    const float* a_dst1 = (const float*)d_in[4];
    const float* b1     = (const float*)d_in[5];
    const float* W2     = (const float*)d_in[6];
    const float* a_src2 = (const float*)d_in[7];
    const float* a_dst2 = (const float*)d_in[8];
    const float* b2     = (const float*)d_in[9];
    const float* G      = (const float*)d_in[10];
    const float* mu     = (const float*)d_in[11];
    float* out = (float*)d_out;

    int N = in_sizes[0] / 256;
    int E = in_sizes[1] / 2;
    const int* src = ei;
    const int* dst = ei + E;

    int gemm_bx = (N + 63) / 64;
    int warp_blocks_nodes = (N * 32 + 255) / 256;
    int edge_blocks = (E + N + 7) / 8;
    int node_elem_blocks = (int)(((size_t)N * 256 + 255) / 256);

    zero_kernel<<<2048, 256>>>(N);

    // ---- layer 1 ----
    sgemm_nt64<<<dim3(gemm_bx, 4), 256>>>(x, W1, /*asel=*/0, /*csel=*/0, N);
    alpha_l1<<<warp_blocks_nodes, 256>>>(a_src1, a_dst1, N);
    edge_l1<<<edge_blocks, 256>>>(src, dst, E, N);
    epi_l1<<<node_elem_blocks, 256>>>(b1, N);

    // ---- layer 2 ----
    sgemm_nt64<<<dim3(gemm_bx, 4), 256>>>(nullptr, W2, /*asel=*/1, /*csel=*/1, N);
    alpha_l2<<<warp_blocks_nodes, 256>>>(a_src2, a_dst2, N);
    edge_l2<<<edge_blocks, 256>>>(src, dst, E, N);
    epi_l2<<<node_elem_blocks, 256>>>(b2, N);

    // ---- projection + cosine ----
    gemm_g_cos<<<dim3(gemm_bx, 8), 256>>>(G, mu, out, N);
}

// round 3
// speedup vs baseline: 1.5830x; 1.5830x over previous
#include <cuda_runtime.h>
#include <math.h>

#define NMAX 50000
#define EMAX 800000

// ---------------- scratch (device globals: no runtime allocation allowed) ----------------
__device__ __align__(16) float g_h1[(size_t)NMAX * 256];
__device__ __align__(16) float g_z1[(size_t)NMAX * 256];
__device__ __align__(16) float g_h2[(size_t)NMAX * 256];
__device__ __align__(16) float g_z2[(size_t)NMAX * 256];
__device__ __align__(16) float g_as1[NMAX * 2];
__device__ __align__(16) float g_ad1[NMAX * 2];
__device__ __align__(16) float g_as2[NMAX];
__device__ __align__(16) float g_ad2[NMAX];
// CSR by destination
__device__ int g_deg[NMAX];
__device__ int g_off[NMAX + 1];
__device__ int g_cur[NMAX];
__device__ int g_csr[EMAX];

// ---------------- CSR build ----------------
__global__ void zero_deg(int N) {
    int i = blockIdx.x * blockDim.x + threadIdx.x;
    if (i < N) g_deg[i] = 0;
}

__global__ void hist_kernel(const int* __restrict__ dst, int E) {
    int e = blockIdx.x * blockDim.x + threadIdx.x;
    if (e < E) atomicAdd(&g_deg[dst[e]], 1);
}

// single-block exclusive scan (N <= 50000, ~49 chunks of 1024)
__global__ void scan_kernel(int N) {
    __shared__ int sh[1024];
    __shared__ int carry_sh;
    int tid = threadIdx.x;
    if (tid == 0) carry_sh = 0;
    __syncthreads();
    for (int base = 0; base < N; base += 1024) {
        int i = base + tid;
        int v = (i < N) ? g_deg[i] : 0;
        sh[tid] = v;
        __syncthreads();
        for (int o = 1; o < 1024; o <<= 1) {
            int t = (tid >= o) ? sh[tid - o] : 0;
            __syncthreads();
            sh[tid] += t;
            __syncthreads();
        }
        int carry = carry_sh;
        if (i < N) {
            int excl = carry + sh[tid] - v;
            g_off[i] = excl;
            g_cur[i] = excl;
        }
        __syncthreads();
        if (tid == 1023) carry_sh = carry + sh[1023];
        __syncthreads();
    }
    if (tid == 0) g_off[N] = carry_sh;
}

__global__ void scatter_kernel(const int* __restrict__ src, const int* __restrict__ dst, int E) {
    int e = blockIdx.x * blockDim.x + threadIdx.x;
    if (e >= E) return;
    int pos = atomicAdd(&g_cur[dst[e]], 1);
    g_csr[pos] = src[e];
}

// ---------------- SGEMM: C[n][o] = sum_k A[n][k] * B[o][k]; K=O=256 ----------------
__global__ __launch_bounds__(256) void sgemm_nt64(
    const float* __restrict__ Aext, const float* __restrict__ B,
    int asel, int csel, int N)
{
    const int BM = 64, BK = 32, K = 256, O = 256;
    const float* A = (asel == 0) ? Aext : g_z1;
    float* C = (csel == 0) ? g_h1 : g_h2;

    __shared__ float As[BK][BM + 4];
    __shared__ float Bs[BK][BM + 4];
    int bm = blockIdx.x * BM;
    int bn = blockIdx.y * 64;
    int tid = threadIdx.x;
    int tr = tid >> 4, tc = tid & 15;

    float acc[4][4];
#pragma unroll
    for (int i = 0; i < 4; i++)
#pragma unroll
        for (int j = 0; j < 4; j++) acc[i][j] = 0.f;

    for (int kt = 0; kt < K; kt += BK) {
#pragma unroll
        for (int i = 0; i < 2; i++) {
            int e = tid + i * 256;
            int row = e >> 3, kq = e & 7;
            int gn = bm + row;
            float4 v = make_float4(0.f, 0.f, 0.f, 0.f);
            if (gn < N) v = *(const float4*)(A + (size_t)gn * K + kt + kq * 4);
            As[kq * 4 + 0][row] = v.x; As[kq * 4 + 1][row] = v.y;
            As[kq * 4 + 2][row] = v.z; As[kq * 4 + 3][row] = v.w;
        }
#pragma unroll
        for (int i = 0; i < 2; i++) {
            int e = tid + i * 256;
            int row = e >> 3, kq = e & 7;
            float4 v = *(const float4*)(B + (size_t)(bn + row) * K + kt + kq * 4);
            Bs[kq * 4 + 0][row] = v.x; Bs[kq * 4 + 1][row] = v.y;
            Bs[kq * 4 + 2][row] = v.z; Bs[kq * 4 + 3][row] = v.w;
        }
        __syncthreads();
#pragma unroll
        for (int kk = 0; kk < BK; kk++) {
            float4 a = *(const float4*)&As[kk][tr * 4];
            float4 b = *(const float4*)&Bs[kk][tc * 4];
            float av[4] = {a.x, a.y, a.z, a.w};
            float bv[4] = {b.x, b.y, b.z, b.w};
#pragma unroll
            for (int i = 0; i < 4; i++)
#pragma unroll
                for (int j = 0; j < 4; j++) acc[i][j] += av[i] * bv[j];
        }
        __syncthreads();
    }
#pragma unroll
    for (int i = 0; i < 4; i++) {
        int gn = bm + tr * 4 + i;
        if (gn < N) {
            float4 v = make_float4(acc[i][0], acc[i][1], acc[i][2], acc[i][3]);
            *(float4*)(C + (size_t)gn * O + bn + tc * 4) = v;
        }
    }
}

// ---------------- attention scalars ----------------
__global__ void alpha_l1(const float* __restrict__ asv, const float* __restrict__ adv, int N) {
    int w = (int)(((size_t)blockIdx.x * blockDim.x + threadIdx.x) >> 5);
    int lane = threadIdx.x & 31;
    if (w >= N) return;
    const float* row = g_h1 + (size_t)w * 256;
    float s0 = 0.f, s1 = 0.f, d0 = 0.f, d1 = 0.f;
#pragma unroll
    for (int t = lane; t < 128; t += 32) {
        float v0 = row[t], v1 = row[128 + t];
        s0 += v0 * asv[t];       d0 += v0 * adv[t];
        s1 += v1 * asv[128 + t]; d1 += v1 * adv[128 + t];
    }
#pragma unroll
    for (int o = 16; o; o >>= 1) {
        s0 += __shfl_xor_sync(0xffffffffu, s0, o);
        s1 += __shfl_xor_sync(0xffffffffu, s1, o);
        d0 += __shfl_xor_sync(0xffffffffu, d0, o);
        d1 += __shfl_xor_sync(0xffffffffu, d1, o);
    }
    if (lane == 0) {
        g_as1[w * 2] = s0; g_as1[w * 2 + 1] = s1;
        g_ad1[w * 2] = d0; g_ad1[w * 2 + 1] = d1;
    }
}

__global__ void alpha_l2(const float* __restrict__ asv, const float* __restrict__ adv, int N) {
    int w = (int)(((size_t)blockIdx.x * blockDim.x + threadIdx.x) >> 5);
    int lane = threadIdx.x & 31;
    if (w >= N) return;
    const float* row = g_h2 + (size_t)w * 256;
    float s = 0.f, d = 0.f;
#pragma unroll
    for (int t = lane; t < 256; t += 32) {
        float v = row[t];
        s += v * asv[t]; d += v * adv[t];
    }
#pragma unroll
    for (int o = 16; o; o >>= 1) {
        s += __shfl_xor_sync(0xffffffffu, s, o);
        d += __shfl_xor_sync(0xffffffffu, d, o);
    }
    if (lane == 0) { g_as2[w] = s; g_ad2[w] = d; }
}

// ---------------- CSR gather, layer 1: one warp per destination node ----------------
// z1[n] = lrelu( (sum_e p_e * h1[src_e]) / (sum_e p_e) + b1 ), incl. self-loop
__global__ __launch_bounds__(256) void gather_l1(const float* __restrict__ b1, int N) {
    int n = (int)(((size_t)blockIdx.x * blockDim.x + threadIdx.x) >> 5);
    int lane = threadIdx.x & 31;
    if (n >= N) return;
    float ad0 = g_ad1[2 * n], ad1v = g_ad1[2 * n + 1];
    int beg = g_off[n], end = g_off[n + 1];
    float4 acc0 = make_float4(0.f, 0.f, 0.f, 0.f);
    float4 acc1 = make_float4(0.f, 0.f, 0.f, 0.f);
    float sum0 = 0.f, sum1 = 0.f;
#pragma unroll 2
    for (int j = beg; j < end; j++) {
        int s = __ldg(&g_csr[j]);
        float e0 = g_as1[2 * s] + ad0;
        float e1 = g_as1[2 * s + 1] + ad1v;
        e0 = e0 > 0.f ? e0 : 0.2f * e0;
        e1 = e1 > 0.f ? e1 : 0.2f * e1;
        float p0 = __expf(e0), p1 = __expf(e1);
        sum0 += p0; sum1 += p1;
        const float4* hs = (const float4*)(g_h1 + (size_t)s * 256);
        float4 v0 = __ldg(&hs[lane]);
        float4 v1 = __ldg(&hs[32 + lane]);
        acc0.x += p0 * v0.x; acc0.y += p0 * v0.y; acc0.z += p0 * v0.z; acc0.w += p0 * v0.w;
        acc1.x += p1 * v1.x; acc1.y += p1 * v1.y; acc1.z += p1 * v1.z; acc1.w += p1 * v1.w;
    }
    {   // self loop
        float e0 = g_as1[2 * n] + ad0;
        float e1 = g_as1[2 * n + 1] + ad1v;
        e0 = e0 > 0.f ? e0 : 0.2f * e0;
        e1 = e1 > 0.f ? e1 : 0.2f * e1;
        float p0 = __expf(e0), p1 = __expf(e1);
        sum0 += p0; sum1 += p1;
        const float4* hs = (const float4*)(g_h1 + (size_t)n * 256);
        float4 v0 = hs[lane], v1 = hs[32 + lane];
        acc0.x += p0 * v0.x; acc0.y += p0 * v0.y; acc0.z += p0 * v0.z; acc0.w += p0 * v0.w;
        acc1.x += p1 * v1.x; acc1.y += p1 * v1.y; acc1.z += p1 * v1.z; acc1.w += p1 * v1.w;
    }
    float r0 = 1.f / sum0, r1 = 1.f / sum1;
    float4 bb0 = *(const float4*)(b1 + lane * 4);
    float4 bb1 = *(const float4*)(b1 + 128 + lane * 4);
    float4 o0, o1;
    o0.x = acc0.x * r0 + bb0.x; o0.y = acc0.y * r0 + bb0.y;
    o0.z = acc0.z * r0 + bb0.z; o0.w = acc0.w * r0 + bb0.w;
    o1.x = acc1.x * r1 + bb1.x; o1.y = acc1.y * r1 + bb1.y;
    o1.z = acc1.z * r1 + bb1.z; o1.w = acc1.w * r1 + bb1.w;
    o0.x = o0.x > 0.f ? o0.x : 0.01f * o0.x; o0.y = o0.y > 0.f ? o0.y : 0.01f * o0.y;
    o0.z = o0.z > 0.f ? o0.z : 0.01f * o0.z; o0.w = o0.w > 0.f ? o0.w : 0.01f * o0.w;
    o1.x = o1.x > 0.f ? o1.x : 0.01f * o1.x; o1.y = o1.y > 0.f ? o1.y : 0.01f * o1.y;
    o1.z = o1.z > 0.f ? o1.z : 0.01f * o1.z; o1.w = o1.w > 0.f ? o1.w : 0.01f * o1.w;
    float4* zp = (float4*)(g_z1 + (size_t)n * 256);
    zp[lane] = o0;
    zp[32 + lane] = o1;
}

// ---------------- CSR gather, layer 2 (heads=1, no activation) ----------------
__global__ __launch_bounds__(256) void gather_l2(const float* __restrict__ b2, int N) {
    int n = (int)(((size_t)blockIdx.x * blockDim.x + threadIdx.x) >> 5);
    int lane = threadIdx.x & 31;
    if (n >= N) return;
    float ad = g_ad2[n];
    int beg = g_off[n], end = g_off[n + 1];
    float4 acc0 = make_float4(0.f, 0.f, 0.f, 0.f);
    float4 acc1 = make_float4(0.f, 0.f, 0.f, 0.f);
    float sum = 0.f;
#pragma unroll 2
    for (int j = beg; j < end; j++) {
        int s = __ldg(&g_csr[j]);
        float e = g_as2[s] + ad;
        e = e > 0.f ? e : 0.2f * e;
        float p = __expf(e);
        sum += p;
        const float4* hs = (const float4*)(g_h2 + (size_t)s * 256);
        float4 v0 = __ldg(&hs[lane]);
        float4 v1 = __ldg(&hs[32 + lane]);
        acc0.x += p * v0.x; acc0.y += p * v0.y; acc0.z += p * v0.z; acc0.w += p * v0.w;
        acc1.x += p * v1.x; acc1.y += p * v1.y; acc1.z += p * v1.z; acc1.w += p * v1.w;
    }
    {   // self loop
        float e = g_as2[n] + ad;
        e = e > 0.f ? e : 0.2f * e;
        float p = __expf(e);
        sum += p;
        const float4* hs = (const float4*)(g_h2 + (size_t)n * 256);
        float4 v0 = hs[lane], v1 = hs[32 + lane];
        acc0.x += p * v0.x; acc0.y += p * v0.y; acc0.z += p * v0.z; acc0.w += p * v0.w;
        acc1.x += p * v1.x; acc1.y += p * v1.y; acc1.z += p * v1.z; acc1.w += p * v1.w;
    }
    float r = 1.f / sum;
    float4 bb0 = *(const float4*)(b2 + lane * 4);
    float4 bb1 = *(const float4*)(b2 + 128 + lane * 4);
    float4 o0, o1;
    o0.x = acc0.x * r + bb0.x; o0.y = acc0.y * r + bb0.y;
    o0.z = acc0.z * r + bb0.z; o0.w = acc0.w * r + bb0.w;
    o1.x = acc1.x * r + bb1.x; o1.y = acc1.y * r + bb1.y;
    o1.z = acc1.z * r + bb1.z; o1.w = acc1.w * r + bb1.w;
    float4* zp = (float4*)(g_z2 + (size_t)n * 256);
    zp[lane] = o0;
    zp[32 + lane] = o1;
}

// ---------------- fused projection + cosine similarity ----------------
__global__ __launch_bounds__(256) void gemm_g_cos(
    const float* __restrict__ G, const float* __restrict__ mu,
    float* __restrict__ out, int N)
{
    const int BM = 64, BK = 32, K = 256, OC = 1024;
    __shared__ float As[BK][BM + 4];
    __shared__ float Bs[BK][128 + 4];
    int bm = blockIdx.x * BM;
    int kb = blockIdx.y;        // 0..7
    int bn = kb * 128;
    int tid = threadIdx.x;
    int tr = tid >> 4, tc = tid & 15;

    float acc[4][8];
#pragma unroll
    for (int i = 0; i < 4; i++)
#pragma unroll
        for (int j = 0; j < 8; j++) acc[i][j] = 0.f;

    for (int kt = 0; kt < K; kt += BK) {
#pragma unroll
        for (int i = 0; i < 2; i++) {
            int e = tid + i * 256;
            int row = e >> 3, kq = e & 7;
            int gn = bm + row;
            float4 v = make_float4(0.f, 0.f, 0.f, 0.f);
            if (gn < N) v = *(const float4*)(g_z2 + (size_t)gn * K + kt + kq * 4);
            As[kq * 4 + 0][row] = v.x; As[kq * 4 + 1][row] = v.y;
            As[kq * 4 + 2][row] = v.z; As[kq * 4 + 3][row] = v.w;
        }
#pragma unroll
        for (int i = 0; i < 4; i++) {
            int e = tid + i * 256;
            int row = e >> 5, cq = e & 31;
            float4 v = *(const float4*)(G + (size_t)(kt + row) * OC + bn + cq * 4);
            *(float4*)&Bs[row][cq * 4] = v;
        }
        __syncthreads();
#pragma unroll
        for (int kk = 0; kk < BK; kk++) {
            float4 a  = *(const float4*)&As[kk][tr * 4];
            float4 b0 = *(const float4*)&Bs[kk][tc * 8];
            float4 b1 = *(const float4*)&Bs[kk][tc * 8 + 4];
            float av[4] = {a.x, a.y, a.z, a.w};
            float bv[8] = {b0.x, b0.y, b0.z, b0.w, b1.x, b1.y, b1.z, b1.w};
#pragma unroll
            for (int i = 0; i < 4; i++)
#pragma unroll
                for (int j = 0; j < 8; j++) acc[i][j] += av[i] * bv[j];
        }
        __syncthreads();
    }

    const float* muk = mu + kb * 128;
    float mj[8], musq = 0.f;
#pragma unroll
    for (int j = 0; j < 8; j++) { mj[j] = muk[tc * 8 + j]; musq += mj[j] * mj[j]; }
    float num[4], sq[4];
#pragma unroll
    for (int i = 0; i < 4; i++) {
        float n_ = 0.f, s_ = 0.f;
#pragma unroll
        for (int j = 0; j < 8; j++) { n_ += acc[i][j] * mj[j]; s_ += acc[i][j] * acc[i][j]; }
        num[i] = n_; sq[i] = s_;
    }
#pragma unroll
    for (int o = 8; o; o >>= 1) {
        musq += __shfl_xor_sync(0xffffffffu, musq, o);
#pragma unroll
        for (int i = 0; i < 4; i++) {
            num[i] += __shfl_xor_sync(0xffffffffu, num[i], o);
            sq[i]  += __shfl_xor_sync(0xffffffffu, sq[i], o);
        }
    }
    if (tc == 0) {
        float mun = sqrtf(musq);
#pragma unroll
        for (int i = 0; i < 4; i++) {
            int gn = bm + tr * 4 + i;
            if (gn < N) {
                float denom = fmaxf(sqrtf(sq[i]) * mun, 1e-8f);
                out[(size_t)gn * 8 + kb] = num[i] / denom;
            }
        }
    }
}

// ---------------- launch ----------------
extern "C" void kernel_launch(void* const* d_in, const int* in_sizes, int n_in,
                              void* d_out, int out_size)
{
    const float* x      = (const float*)d_in[0];
    const int*   ei     = (const int*)d_in[1];      // int32 (JAX x64 disabled)
    const float* W1     = (const float*)d_in[2];
    const float* a_src1 = (const float*)d_in[3];
    const float* a_dst1 = (const float*)d_in[4];
    const float* b1     = (const float*)d_in[5];
    const float* W2     = (const float*)d_in[6];
    const float* a_src2 = (const float*)d_in[7];
    const float* a_dst2 = (const float*)d_in[8];
    const float* b2     = (const float*)d_in[9];
    const float* G      = (const float*)d_in[10];
    const float* mu     = (const float*)d_in[11];
    float* out = (float*)d_out;

    int N = in_sizes[0] / 256;
    int E = in_sizes[1] / 2;
    const int* src = ei;
    const int* dst = ei + E;

    int gemm_bx = (N + 63) / 64;
    int warp_blocks_nodes = (N * 32 + 255) / 256;

    // ---- CSR build (by destination) ----
    zero_deg<<<(N + 255) / 256, 256>>>(N);
    hist_kernel<<<(E + 255) / 256, 256>>>(dst, E);
    scan_kernel<<<1, 1024>>>(N);
    scatter_kernel<<<(E + 255) / 256, 256>>>(src, dst, E);

    // ---- layer 1 ----
    sgemm_nt64<<<dim3(gemm_bx, 4), 256>>>(x, W1, /*asel=*/0, /*csel=*/0, N);
    alpha_l1<<<warp_blocks_nodes, 256>>>(a_src1, a_dst1, N);
    gather_l1<<<warp_blocks_nodes, 256>>>(b1, N);

    // ---- layer 2 ----
    sgemm_nt64<<<dim3(gemm_bx, 4), 256>>>(nullptr, W2, /*asel=*/1, /*csel=*/1, N);
    alpha_l2<<<warp_blocks_nodes, 256>>>(a_src2, a_dst2, N);
    gather_l2<<<warp_blocks_nodes, 256>>>(b2, N);

    // ---- projection + cosine ----
    gemm_g_cos<<<dim3(gemm_bx, 8), 256>>>(G, mu, out, N);
}

// round 5
// speedup vs baseline: 3.1183x; 1.9698x over previous
#include <cuda_runtime.h>
#include <cuda_bf16.h>
#include <cstdint>
#include <math.h>

#define NMAX 50000
#define EMAX 800000

// ================= scratch (device globals) =================
__device__ __align__(16) float g_h1[(size_t)NMAX * 256];
__device__ __align__(16) float g_z1[(size_t)NMAX * 256];
__device__ __align__(16) float g_h2[(size_t)NMAX * 256];
__device__ __align__(16) float g_z2[(size_t)NMAX * 256];
__device__ __align__(16) float g_as1[NMAX * 2];
__device__ __align__(16) float g_ad1[NMAX * 2];
__device__ __align__(16) float g_as2[NMAX];
__device__ __align__(16) float g_ad2[NMAX];
// CSR by destination
__device__ int g_deg[NMAX];
__device__ int g_off[NMAX + 1];
__device__ int g_cur[NMAX];
__device__ int g_csr[EMAX];
// split-bf16 operands
__device__ __align__(16) __nv_bfloat16 g_ahi[(size_t)NMAX * 256];
__device__ __align__(16) __nv_bfloat16 g_alo[(size_t)NMAX * 256];
__device__ __align__(16) __nv_bfloat16 g_bhi[(size_t)1024 * 256];
__device__ __align__(16) __nv_bfloat16 g_blo[(size_t)1024 * 256];

__device__ __forceinline__ uint32_t smem_u32(const void* p) {
    uint32_t a;
    asm("{ .reg .u64 t; cvta.to.shared.u64 t, %1; cvt.u32.u64 %0, t; }" : "=r"(a) : "l"(p));
    return a;
}

// ================= CSR build =================
__global__ void zero_deg(int N) {
    int i = blockIdx.x * blockDim.x + threadIdx.x;
    if (i < N) g_deg[i] = 0;
}
__global__ void hist_kernel(const int* __restrict__ dst, int E) {
    int e = blockIdx.x * blockDim.x + threadIdx.x;
    if (e < E) atomicAdd(&g_deg[dst[e]], 1);
}
__global__ void scan_kernel(int N) {
    __shared__ int sh[1024];
    __shared__ int carry_sh;
    int tid = threadIdx.x;
    if (tid == 0) carry_sh = 0;
    __syncthreads();
    for (int base = 0; base < N; base += 1024) {
        int i = base + tid;
        int v = (i < N) ? g_deg[i] : 0;
        sh[tid] = v;
        __syncthreads();
        for (int o = 1; o < 1024; o <<= 1) {
            int t = (tid >= o) ? sh[tid - o] : 0;
            __syncthreads();
            sh[tid] += t;
            __syncthreads();
        }
        int carry = carry_sh;
        if (i < N) {
            int excl = carry + sh[tid] - v;
            g_off[i] = excl;
            g_cur[i] = excl;
        }
        __syncthreads();
        if (tid == 1023) carry_sh = carry + sh[1023];
        __syncthreads();
    }
    if (tid == 0) g_off[N] = carry_sh;
}
__global__ void scatter_kernel(const int* __restrict__ src, const int* __restrict__ dst, int E) {
    int e = blockIdx.x * blockDim.x + threadIdx.x;
    if (e >= E) return;
    int pos = atomicAdd(&g_cur[dst[e]], 1);
    g_csr[pos] = src[e];
}

// ================= split-bf16 conversions =================
__global__ void split_a(const float* __restrict__ ext, int sel, size_t n) {
    size_t i = (size_t)blockIdx.x * blockDim.x + threadIdx.x;
    if (i >= n) return;
    const float* in = (sel == 0) ? ext : (sel == 1 ? g_z1 : g_z2);
    float v = in[i];
    __nv_bfloat16 h = __float2bfloat16(v);
    g_ahi[i] = h;
    g_alo[i] = __float2bfloat16(v - __bfloat162float(h));
}

__global__ void split_w(const float* __restrict__ W, size_t n) {
    size_t i = (size_t)blockIdx.x * blockDim.x + threadIdx.x;
    if (i >= n) return;
    float v = W[i];
    __nv_bfloat16 h = __float2bfloat16(v);
    g_bhi[i] = h;
    g_blo[i] = __float2bfloat16(v - __bfloat162float(h));
}

// G[256][1024] -> g_bhi/g_blo as [1024][256] (transpose + split)
__global__ void tsplit_g(const float* __restrict__ G) {
    __shared__ float t[32][33];
    int bx = blockIdx.x;   // oc tile (0..31)
    int by = blockIdx.y;   // k tile (0..7)
    int x = threadIdx.x, y = threadIdx.y;   // 32 x 8
#pragma unroll
    for (int i = 0; i < 4; i++)
        t[y + i * 8][x] = G[(size_t)(by * 32 + y + i * 8) * 1024 + bx * 32 + x];
    __syncthreads();
#pragma unroll
    for (int i = 0; i < 4; i++) {
        float v = t[x][y + i * 8];
        size_t idx = (size_t)(bx * 32 + y + i * 8) * 256 + by * 32 + x;
        __nv_bfloat16 h = __float2bfloat16(v);
        g_bhi[idx] = h;
        g_blo[idx] = __float2bfloat16(v - __bfloat162float(h));
    }
}

// ================= HMMA (mma.sync) GEMM =================
// C[m][n] = sum_k A[m][k]*B[n][k], A = g_ahi/g_alo [Nrows][256], B = g_bhi/g_blo
// 3-term split: Ahi*Bhi + Ahi*Blo + Alo*Bhi, fp32 accum.
// BM=128, BN=128, BK=32; 8 warps (4 m x 2 n), warp tile 32x64.
// mode 0: C=g_h1 ; 1: C=g_h2 ; 2: cosine epilogue -> outp[N][8], kb=blockIdx.y

#define TILE_B   10240          // 128 rows * 80B (32 bf16 + 8 pad)
#define STAGE_B  (4 * TILE_B)   // Ahi, Alo, Bhi, Blo
#define SMEM_B   (2 * STAGE_B)  // double buffered (81920 B)

__device__ __forceinline__ void ldsm_x4(uint32_t* r, uint32_t addr) {
    asm volatile("ldmatrix.sync.aligned.m8n8.x4.shared.b16 {%0,%1,%2,%3}, [%4];"
        : "=r"(r[0]), "=r"(r[1]), "=r"(r[2]), "=r"(r[3]) : "r"(addr));
}
__device__ __forceinline__ void ldsm_x2(uint32_t* r, uint32_t addr) {
    asm volatile("ldmatrix.sync.aligned.m8n8.x2.shared.b16 {%0,%1}, [%2];"
        : "=r"(r[0]), "=r"(r[1]) : "r"(addr));
}
__device__ __forceinline__ void mma_bf16(float* c, const uint32_t* a, const uint32_t* b) {
    asm volatile("mma.sync.aligned.m16n8k16.row.col.f32.bf16.bf16.f32 "
        "{%0,%1,%2,%3}, {%4,%5,%6,%7}, {%8,%9}, {%0,%1,%2,%3};"
        : "+f"(c[0]), "+f"(c[1]), "+f"(c[2]), "+f"(c[3])
        : "r"(a[0]), "r"(a[1]), "r"(a[2]), "r"(a[3]), "r"(b[0]), "r"(b[1]));
}

__device__ __forceinline__ void cp16(uint32_t saddr, const void* gaddr, int szbytes) {
    asm volatile("cp.async.cg.shared.global [%0], [%1], 16, %2;"
        :: "r"(saddr), "l"(gaddr), "r"(szbytes));
}

// load one 128x32 bf16 tile (rows grow_base.., zero-fill OOB) into smem tile
__device__ __forceinline__ void load_tile(char* st, const __nv_bfloat16* gsrc,
                                          int grow_base, int grow_limit, int k0, int tid)
{
#pragma unroll
    for (int j = 0; j < 2; j++) {
        int idx = tid * 2 + j;            // 0..511
        int row = idx >> 2, kc = idx & 3;
        int grow = grow_base + row;
        int ok = (grow < grow_limit);
        const __nv_bfloat16* gp = gsrc + (size_t)(ok ? grow : 0) * 256 + k0 + kc * 8;
        uint32_t sa = smem_u32(st + row * 80 + kc * 16);
        cp16(sa, gp, ok ? 16 : 0);
    }
}

__global__ __launch_bounds__(256) void gemm_hmma(
    int Nrows, int mode, const float* __restrict__ mu, float* __restrict__ outp)
{
    extern __shared__ char smem[];
    int tid = threadIdx.x;
    int wid = tid >> 5;
    int lane = tid & 31;
    int warp_m = wid & 3;            // 4 x 32 rows
    int warp_n = wid >> 2;           // 2 x 64 cols
    int bm = blockIdx.x * 128;
    int bn = blockIdx.y * 128;

    float acc[2][8][4];
#pragma unroll
    for (int mt = 0; mt < 2; mt++)
#pragma unroll
        for (int nt = 0; nt < 8; nt++)
#pragma unroll
            for (int j = 0; j < 4; j++) acc[mt][nt][j] = 0.f;

    // prologue: stage 0
    {
        char* s0 = smem;
        load_tile(s0,              g_ahi, bm, Nrows, 0, tid);
        load_tile(s0 + TILE_B,     g_alo, bm, Nrows, 0, tid);
        load_tile(s0 + 2 * TILE_B, g_bhi, bn, 1 << 30, 0, tid);
        load_tile(s0 + 3 * TILE_B, g_blo, bn, 1 << 30, 0, tid);
        asm volatile("cp.async.commit_group;" ::: "memory");
    }

    for (int c = 0; c < 8; c++) {
        if (c < 7) {
            char* sn = smem + ((c + 1) & 1) * STAGE_B;
            int k0 = (c + 1) * 32;
            load_tile(sn,              g_ahi, bm, Nrows, k0, tid);
            load_tile(sn + TILE_B,     g_alo, bm, Nrows, k0, tid);
            load_tile(sn + 2 * TILE_B, g_bhi, bn, 1 << 30, k0, tid);
            load_tile(sn + 3 * TILE_B, g_blo, bn, 1 << 30, k0, tid);
            asm volatile("cp.async.commit_group;" ::: "memory");
            asm volatile("cp.async.wait_group 1;" ::: "memory");
        } else {
            asm volatile("cp.async.wait_group 0;" ::: "memory");
        }
        __syncthreads();

        char* sa_hi = smem + (c & 1) * STAGE_B;
        char* sa_lo = sa_hi + TILE_B;
        char* sb_hi = sa_hi + 2 * TILE_B;
        char* sb_lo = sa_hi + 3 * TILE_B;

#pragma unroll
        for (int ks = 0; ks < 2; ks++) {
            uint32_t ah[2][4], al[2][4];
#pragma unroll
            for (int mt = 0; mt < 2; mt++) {
                int row = warp_m * 32 + mt * 16 + (lane & 7) + ((lane >> 3) & 1) * 8;
                int kc = ks * 2 + (lane >> 4);
                uint32_t off = (uint32_t)(row * 80 + kc * 16);
                ldsm_x4(ah[mt], smem_u32(sa_hi + off));
                ldsm_x4(al[mt], smem_u32(sa_lo + off));
            }
#pragma unroll
            for (int nt = 0; nt < 8; nt++) {
                int lb = lane & 15;
                int brow = warp_n * 64 + nt * 8 + (lb & 7);
                int bkc = ks * 2 + (lb >> 3);
                uint32_t boff = (uint32_t)(brow * 80 + bkc * 16);
                uint32_t bh[2], bl[2];
                ldsm_x2(bh, smem_u32(sb_hi + boff));
                ldsm_x2(bl, smem_u32(sb_lo + boff));
#pragma unroll
                for (int mt = 0; mt < 2; mt++) {
                    mma_bf16(acc[mt][nt], ah[mt], bh);
                    mma_bf16(acc[mt][nt], ah[mt], bl);
                    mma_bf16(acc[mt][nt], al[mt], bh);
                }
            }
        }
        __syncthreads();
    }

    // ================= epilogue =================
    if (mode < 2) {
        float* C = (mode == 0) ? g_h1 : g_h2;
#pragma unroll
        for (int mt = 0; mt < 2; mt++) {
            int r0 = bm + warp_m * 32 + mt * 16 + (lane >> 2);
#pragma unroll
            for (int nt = 0; nt < 8; nt++) {
                int gcol = bn + warp_n * 64 + nt * 8 + (lane & 3) * 2;
                if (r0 < Nrows)
                    *(float2*)(C + (size_t)r0 * 256 + gcol) =
                        make_float2(acc[mt][nt][0], acc[mt][nt][1]);
                if (r0 + 8 < Nrows)
                    *(float2*)(C + (size_t)(r0 + 8) * 256 + gcol) =
                        make_float2(acc[mt][nt][2], acc[mt][nt][3]);
            }
        }
    } else {
        int kb = blockIdx.y;
        const float* muk = mu + kb * 128;
        // partial num/sq per (mt, half)
        float pn[2][2], psq[2][2];
#pragma unroll
        for (int mt = 0; mt < 2; mt++)
#pragma unroll
            for (int h = 0; h < 2; h++) { pn[mt][h] = 0.f; psq[mt][h] = 0.f; }
#pragma unroll
        for (int nt = 0; nt < 8; nt++) {
            int col = warp_n * 64 + nt * 8 + (lane & 3) * 2;
            float m0 = __ldg(&muk[col]), m1 = __ldg(&muk[col + 1]);
#pragma unroll
            for (int mt = 0; mt < 2; mt++) {
                float c0 = acc[mt][nt][0], c1 = acc[mt][nt][1];
                float c2 = acc[mt][nt][2], c3 = acc[mt][nt][3];
                pn[mt][0] += c0 * m0 + c1 * m1;  psq[mt][0] += c0 * c0 + c1 * c1;
                pn[mt][1] += c2 * m0 + c3 * m1;  psq[mt][1] += c2 * c2 + c3 * c3;
            }
        }
        // reduce over lane&3 (cols)
#pragma unroll
        for (int o = 1; o <= 2; o <<= 1) {
#pragma unroll
            for (int mt = 0; mt < 2; mt++)
#pragma unroll
                for (int h = 0; h < 2; h++) {
                    pn[mt][h]  += __shfl_xor_sync(0xffffffffu, pn[mt][h], o);
                    psq[mt][h] += __shfl_xor_sync(0xffffffffu, psq[mt][h], o);
                }
        }
        float2* sred = (float2*)smem;   // [2 warp_n][128 rows]
        __syncthreads();
        if ((lane & 3) == 0) {
#pragma unroll
            for (int mt = 0; mt < 2; mt++)
#pragma unroll
                for (int h = 0; h < 2; h++) {
                    int rl = warp_m * 32 + mt * 16 + h * 8 + (lane >> 2);
                    sred[warp_n * 128 + rl] = make_float2(pn[mt][h], psq[mt][h]);
                }
        }
        __syncthreads();
        if (tid < 128) {
            float2 p0 = sred[tid], p1 = sred[128 + tid];
            float num = p0.x + p1.x;
            float sq  = p0.y + p1.y;
            float musq = 0.f;
#pragma unroll 16
            for (int j = 0; j < 128; j++) {
                float mv = __ldg(&muk[j]);
                musq += mv * mv;
            }
            int m = bm + tid;
            if (m < Nrows)
                outp[(size_t)m * 8 + kb] = num / fmaxf(sqrtf(sq) * sqrtf(musq), 1e-8f);
        }
    }
}

// ================= attention scalars =================
__global__ void alpha_l1(const float* __restrict__ asv, const float* __restrict__ adv, int N) {
    int w = (int)(((size_t)blockIdx.x * blockDim.x + threadIdx.x) >> 5);
    int lane = threadIdx.x & 31;
    if (w >= N) return;
    const float* row = g_h1 + (size_t)w * 256;
    float s0 = 0.f, s1 = 0.f, d0 = 0.f, d1 = 0.f;
#pragma unroll
    for (int t = lane; t < 128; t += 32) {
        float v0 = row[t], v1 = row[128 + t];
        s0 += v0 * asv[t];       d0 += v0 * adv[t];
        s1 += v1 * asv[128 + t]; d1 += v1 * adv[128 + t];
    }
#pragma unroll
    for (int o = 16; o; o >>= 1) {
        s0 += __shfl_xor_sync(0xffffffffu, s0, o);
        s1 += __shfl_xor_sync(0xffffffffu, s1, o);
        d0 += __shfl_xor_sync(0xffffffffu, d0, o);
        d1 += __shfl_xor_sync(0xffffffffu, d1, o);
    }
    if (lane == 0) {
        g_as1[w * 2] = s0; g_as1[w * 2 + 1] = s1;
        g_ad1[w * 2] = d0; g_ad1[w * 2 + 1] = d1;
    }
}

__global__ void alpha_l2(const float* __restrict__ asv, const float* __restrict__ adv, int N) {
    int w = (int)(((size_t)blockIdx.x * blockDim.x + threadIdx.x) >> 5);
    int lane = threadIdx.x & 31;
    if (w >= N) return;
    const float* row = g_h2 + (size_t)w * 256;
    float s = 0.f, d = 0.f;
#pragma unroll
    for (int t = lane; t < 256; t += 32) {
        float v = row[t];
        s += v * asv[t]; d += v * adv[t];
    }
#pragma unroll
    for (int o = 16; o; o >>= 1) {
        s += __shfl_xor_sync(0xffffffffu, s, o);
        d += __shfl_xor_sync(0xffffffffu, d, o);
    }
    if (lane == 0) { g_as2[w] = s; g_ad2[w] = d; }
}

// ================= CSR gather layer 1 =================
__global__ __launch_bounds__(256) void gather_l1(const float* __restrict__ b1, int N) {
    int n = (int)(((size_t)blockIdx.x * blockDim.x + threadIdx.x) >> 5);
    int lane = threadIdx.x & 31;
    if (n >= N) return;
    float ad0 = g_ad1[2 * n], ad1v = g_ad1[2 * n + 1];
    int beg = g_off[n], end = g_off[n + 1];
    float4 acc0 = make_float4(0.f, 0.f, 0.f, 0.f);
    float4 acc1 = make_float4(0.f, 0.f, 0.f, 0.f);
    float sum0 = 0.f, sum1 = 0.f;
#pragma unroll 2
    for (int j = beg; j < end; j++) {
        int s = __ldg(&g_csr[j]);
        float e0 = g_as1[2 * s] + ad0;
        float e1 = g_as1[2 * s + 1] + ad1v;
        e0 = e0 > 0.f ? e0 : 0.2f * e0;
        e1 = e1 > 0.f ? e1 : 0.2f * e1;
        float p0 = __expf(e0), p1 = __expf(e1);
        sum0 += p0; sum1 += p1;
        const float4* hs = (const float4*)(g_h1 + (size_t)s * 256);
        float4 v0 = __ldg(&hs[lane]);
        float4 v1 = __ldg(&hs[32 + lane]);
        acc0.x += p0 * v0.x; acc0.y += p0 * v0.y; acc0.z += p0 * v0.z; acc0.w += p0 * v0.w;
        acc1.x += p1 * v1.x; acc1.y += p1 * v1.y; acc1.z += p1 * v1.z; acc1.w += p1 * v1.w;
    }
    {
        float e0 = g_as1[2 * n] + ad0;
        float e1 = g_as1[2 * n + 1] + ad1v;
        e0 = e0 > 0.f ? e0 : 0.2f * e0;
        e1 = e1 > 0.f ? e1 : 0.2f * e1;
        float p0 = __expf(e0), p1 = __expf(e1);
        sum0 += p0; sum1 += p1;
        const float4* hs = (const float4*)(g_h1 + (size_t)n * 256);
        float4 v0 = hs[lane], v1 = hs[32 + lane];
        acc0.x += p0 * v0.x; acc0.y += p0 * v0.y; acc0.z += p0 * v0.z; acc0.w += p0 * v0.w;
        acc1.x += p1 * v1.x; acc1.y += p1 * v1.y; acc1.z += p1 * v1.z; acc1.w += p1 * v1.w;
    }
    float r0 = 1.f / sum0, r1 = 1.f / sum1;
    float4 bb0 = *(const float4*)(b1 + lane * 4);
    float4 bb1 = *(const float4*)(b1 + 128 + lane * 4);
    float4 o0, o1;
    o0.x = acc0.x * r0 + bb0.x; o0.y = acc0.y * r0 + bb0.y;
    o0.z = acc0.z * r0 + bb0.z; o0.w = acc0.w * r0 + bb0.w;
    o1.x = acc1.x * r1 + bb1.x; o1.y = acc1.y * r1 + bb1.y;
    o1.z = acc1.z * r1 + bb1.z; o1.w = acc1.w * r1 + bb1.w;
    o0.x = o0.x > 0.f ? o0.x : 0.01f * o0.x; o0.y = o0.y > 0.f ? o0.y : 0.01f * o0.y;
    o0.z = o0.z > 0.f ? o0.z : 0.01f * o0.z; o0.w = o0.w > 0.f ? o0.w : 0.01f * o0.w;
    o1.x = o1.x > 0.f ? o1.x : 0.01f * o1.x; o1.y = o1.y > 0.f ? o1.y : 0.01f * o1.y;
    o1.z = o1.z > 0.f ? o1.z : 0.01f * o1.z; o1.w = o1.w > 0.f ? o1.w : 0.01f * o1.w;
    float4* zp = (float4*)(g_z1 + (size_t)n * 256);
    zp[lane] = o0;
    zp[32 + lane] = o1;
}

// ================= CSR gather layer 2 =================
__global__ __launch_bounds__(256) void gather_l2(const float* __restrict__ b2, int N) {
    int n = (int)(((size_t)blockIdx.x * blockDim.x + threadIdx.x) >> 5);
    int lane = threadIdx.x & 31;
    if (n >= N) return;
    float ad = g_ad2[n];
    int beg = g_off[n], end = g_off[n + 1];
    float4 acc0 = make_float4(0.f, 0.f, 0.f, 0.f);
    float4 acc1 = make_float4(0.f, 0.f, 0.f, 0.f);
    float sum = 0.f;
#pragma unroll 2
    for (int j = beg; j < end; j++) {
        int s = __ldg(&g_csr[j]);
        float e = g_as2[s] + ad;
        e = e > 0.f ? e : 0.2f * e;
        float p = __expf(e);
        sum += p;
        const float4* hs = (const float4*)(g_h2 + (size_t)s * 256);
        float4 v0 = __ldg(&hs[lane]);
        float4 v1 = __ldg(&hs[32 + lane]);
        acc0.x += p * v0.x; acc0.y += p * v0.y; acc0.z += p * v0.z; acc0.w += p * v0.w;
        acc1.x += p * v1.x; acc1.y += p * v1.y; acc1.z += p * v1.z; acc1.w += p * v1.w;
    }
    {
        float e = g_as2[n] + ad;
        e = e > 0.f ? e : 0.2f * e;
        float p = __expf(e);
        sum += p;
        const float4* hs = (const float4*)(g_h2 + (size_t)n * 256);
        float4 v0 = hs[lane], v1 = hs[32 + lane];
        acc0.x += p * v0.x; acc0.y += p * v0.y; acc0.z += p * v0.z; acc0.w += p * v0.w;
        acc1.x += p * v1.x; acc1.y += p * v1.y; acc1.z += p * v1.z; acc1.w += p * v1.w;
    }
    float r = 1.f / sum;
    float4 bb0 = *(const float4*)(b2 + lane * 4);
    float4 bb1 = *(const float4*)(b2 + 128 + lane * 4);
    float4 o0, o1;
    o0.x = acc0.x * r + bb0.x; o0.y = acc0.y * r + bb0.y;
    o0.z = acc0.z * r + bb0.z; o0.w = acc0.w * r + bb0.w;
    o1.x = acc1.x * r + bb1.x; o1.y = acc1.y * r + bb1.y;
    o1.z = acc1.z * r + bb1.z; o1.w = acc1.w * r + bb1.w;
    float4* zp = (float4*)(g_z2 + (size_t)n * 256);
    zp[lane] = o0;
    zp[32 + lane] = o1;
}

// ================= launch =================
extern "C" void kernel_launch(void* const* d_in, const int* in_sizes, int n_in,
                              void* d_out, int out_size)
{
    const float* x      = (const float*)d_in[0];
    const int*   ei     = (const int*)d_in[1];      // int32 (JAX x64 disabled)
    const float* W1     = (const float*)d_in[2];
    const float* a_src1 = (const float*)d_in[3];
    const float* a_dst1 = (const float*)d_in[4];
    const float* b1     = (const float*)d_in[5];
    const float* W2     = (const float*)d_in[6];
    const float* a_src2 = (const float*)d_in[7];
    const float* a_dst2 = (const float*)d_in[8];
    const float* b2     = (const float*)d_in[9];
    const float* G      = (const float*)d_in[10];
    const float* mu     = (const float*)d_in[11];
    float* out = (float*)d_out;

    int N = in_sizes[0] / 256;
    int E = in_sizes[1] / 2;
    const int* src = ei;
    const int* dst = ei + E;

    static bool attr_set = false;
    if (!attr_set) {
        cudaFuncSetAttribute(gemm_hmma, cudaFuncAttributeMaxDynamicSharedMemorySize, SMEM_B);
        attr_set = true;
    }

    size_t nel = (size_t)N * 256;
    int ablk = (int)((nel + 255) / 256);
    int gemm_bx = (N + 127) / 128;
    int warp_blocks_nodes = (N * 32 + 255) / 256;

    // ---- CSR build (by destination) ----
    zero_deg<<<(N + 255) / 256, 256>>>(N);
    hist_kernel<<<(E + 255) / 256, 256>>>(dst, E);
    scan_kernel<<<1, 1024>>>(N);
    scatter_kernel<<<(E + 255) / 256, 256>>>(src, dst, E);

    // ---- layer 1: h1 = x @ W1^T ----
    split_a<<<ablk, 256>>>(x, 0, nel);
    split_w<<<(256 * 256 + 255) / 256, 256>>>(W1, 256 * 256);
    gemm_hmma<<<dim3(gemm_bx, 2), 256, SMEM_B>>>(N, 0, nullptr, nullptr);
    alpha_l1<<<warp_blocks_nodes, 256>>>(a_src1, a_dst1, N);
    gather_l1<<<warp_blocks_nodes, 256>>>(b1, N);

    // ---- layer 2: h2 = z1 @ W2^T ----
    split_a<<<ablk, 256>>>(nullptr, 1, nel);
    split_w<<<(256 * 256 + 255) / 256, 256>>>(W2, 256 * 256);
    gemm_hmma<<<dim3(gemm_bx, 2), 256, SMEM_B>>>(N, 1, nullptr, nullptr);
    alpha_l2<<<warp_blocks_nodes, 256>>>(a_src2, a_dst2, N);
    gather_l2<<<warp_blocks_nodes, 256>>>(b2, N);

    // ---- projection + cosine: out = cos(z2 @ G, mu) ----
    split_a<<<ablk, 256>>>(nullptr, 2, nel);
    tsplit_g<<<dim3(32, 8), dim3(32, 8)>>>(G);
    gemm_hmma<<<dim3(gemm_bx, 8), 256, SMEM_B>>>(N, 2, mu, out);
}